// round 12
// baseline (speedup 1.0000x reference)
#include <cuda_runtime.h>
#include <cuda_fp16.h>
#include <math.h>

// Problem constants
#define Bn 8
#define Ln 4096
#define Hn 1024
#define Nn 32
#define Tn 128            // chunk length
#define Cc 32             // chunks (Tn*Cc == Ln)
#define BC 256            // B*C columns
#define KD 192            // main GEMM K dim: 128 (u) + 64 (states)

// ---- persistent device buffers (no allocs allowed) ----
__device__ __align__(256) __half  g_V[(size_t)Hn * BC * 128];  // per-h u operand [256][128]
__device__ __align__(256) __half  g_yT16[(size_t)Hn * BC * Tn];// per-h output [256][128] fp16

// ---- small helpers ----
static __device__ __forceinline__ unsigned smem_u32(const void* p) {
    unsigned r;
    asm("{ .reg .u64 t; cvta.to.shared.u64 t, %1; cvt.u32.u64 %0, t; }"
        : "=r"(r) : "l"(p));
    return r;
}
static __device__ __forceinline__ void cp16(unsigned dst, const void* src) {
    asm volatile("cp.async.cg.shared.global [%0], [%1], 16;" :: "r"(dst), "l"(src));
}
static __device__ __forceinline__ void cp_commit() {
    asm volatile("cp.async.commit_group;");
}
static __device__ __forceinline__ void cp_wait_all() {
    asm volatile("cp.async.wait_group 0;");
}
static __device__ __forceinline__ void ldmA(unsigned addr, unsigned& r0, unsigned& r1,
                                            unsigned& r2, unsigned& r3) {
    asm volatile("ldmatrix.sync.aligned.m8n8.x4.shared.b16 {%0,%1,%2,%3}, [%4];"
                 : "=r"(r0), "=r"(r1), "=r"(r2), "=r"(r3) : "r"(addr));
}
static __device__ __forceinline__ void ldmB(unsigned addr, unsigned& r0, unsigned& r1) {
    asm volatile("ldmatrix.sync.aligned.m8n8.x2.shared.b16 {%0,%1}, [%2];"
                 : "=r"(r0), "=r"(r1) : "r"(addr));
}
static __device__ __forceinline__ void mma16816(float* d, const unsigned* a,
                                                const unsigned* b) {
    asm volatile(
        "mma.sync.aligned.m16n8k16.row.col.f32.f16.f16.f32 "
        "{%0,%1,%2,%3}, {%4,%5,%6,%7}, {%8,%9}, {%0,%1,%2,%3};"
        : "+f"(d[0]), "+f"(d[1]), "+f"(d[2]), "+f"(d[3])
        : "r"(a[0]), "r"(a[1]), "r"(a[2]), "r"(a[3]), "r"(b[0]), "r"(b[1]));
}

// Fast branch-free erf-GELU (A&S 7.1.26, |eps_erf| < 1.5e-7)
static __device__ __forceinline__ float gelu_erf(float v) {
    float z = fabsf(v) * 0.70710678118654752440f;
    float t = __fdividef(1.0f, fmaf(0.3275911f, z, 1.0f));
    float p = fmaf(1.061405429f, t, -1.453152027f);
    p = fmaf(p, t, 1.421413741f);
    p = fmaf(p, t, -0.284496736f);
    p = fmaf(p, t, 0.254829592f);
    p *= t;
    float e = __expf(-z * z);
    float erfz = fmaf(-p, e, 1.0f);          // erf(|v|/sqrt2)
    float erfv = copysignf(erfz, v);
    return 0.5f * v * (1.0f + erfv);
}

// Per-mode recurrence params: w = exp(dt*A), c' = C*(w-1)/A
struct ModeParams {
    float ar[32], ai[32];       // log|w|, arg w
    float wr[32], wi[32];       // w
    float cr[32], ci[32];       // c'
};
static __device__ __forceinline__ void compute_params(
    ModeParams& P, int h, int n,
    const float* __restrict__ log_dt, const float* __restrict__ A_real,
    const float* __restrict__ A_imag, const float* __restrict__ C_real,
    const float* __restrict__ C_imag) {
    int idx = h * Nn + n;
    float dt = expf(log_dt[h]);
    float Ar = -expf(A_real[idx]);
    float Ai = A_imag[idx];
    float ar = Ar * dt, ai = Ai * dt;
    float er = expf(ar);
    float sn, cs;
    sincosf(ai, &sn, &cs);
    float wr = er * cs, wi = er * sn;
    float den = Ar * Ar + Ai * Ai;
    float e1r = wr - 1.0f, e1i = wi;
    float qr = (e1r * Ar + e1i * Ai) / den;
    float qi = (e1i * Ar - e1r * Ai) / den;
    float Cr = C_real[idx], Ci = C_imag[idx];
    P.ar[n] = ar; P.ai[n] = ai;
    P.wr[n] = wr; P.wi[n] = wi;
    P.cr[n] = Cr * qr - Ci * qi;
    P.ci[n] = Cr * qi + Ci * qr;
}

// =====================================================================
// k_transpose: u (b,l,h) fp32 -> g_V[h][bc][0..128) fp16  (h-tile offset)
// =====================================================================
__global__ void __launch_bounds__(256)
k_transpose(const float* __restrict__ u, int ht0) {
    int ht = blockIdx.x + ht0, c = blockIdx.y, b = blockIdx.z;
    __shared__ __half ts[32][136];
    int lane = threadIdx.x & 31;
    int r = threadIdx.x >> 5;

    const float* up = u + ((size_t)b * Ln + (size_t)c * Tn) * Hn + ht * 32;
#pragma unroll
    for (int j0 = 0; j0 < Tn; j0 += 8) {
        int j = j0 + r;
        ts[lane][j] = __float2half(up[(size_t)j * Hn + lane]);
    }
    __syncthreads();

    int row = threadIdx.x >> 3;
    int ch = threadIdx.x & 7;
    int bc = b * Cc + c;
    __half* dst = g_V + ((size_t)(ht * 32 + row) * BC + bc) * 128;
    reinterpret_cast<uint4*>(dst)[ch] =
        *reinterpret_cast<const uint4*>(&ts[row][ch * 8]);
    reinterpret_cast<uint4*>(dst)[ch + 8] =
        *reinterpret_cast<const uint4*>(&ts[row][(ch + 8) * 8]);
}

// =====================================================================
// k_fused: one block per (h, batch-half). Half = 4 sequences = 128 bc.
// =====================================================================
#define LDB  200     // Bs row stride (halves)
#define LDA1 136     // Enc row stride
#define LDX  130     // Xl fp32 row stride
#define LDA2 200     // main A row stride
#define LDO  136     // epilogue staging stride
#define R1_OFF (128 * LDB)                    // halves
#define SMEM_FUSED ((128 * LDB) * 2 + 51200)  // bytes = 102400

__global__ void __launch_bounds__(256, 2)
k_fused(const float* __restrict__ log_dt, const float* __restrict__ A_real,
        const float* __restrict__ A_imag, const float* __restrict__ C_real,
        const float* __restrict__ C_imag, int h0) {
    int h = blockIdx.x + h0;
    int half = blockIdx.y;
    int tid = threadIdx.x;
    extern __shared__ __half sm[];
    __half* Bs = sm;                 // [128][LDB]
    __half* R1 = sm + R1_OFF;        // 51200B scratch: Enc / Xl / A / epilogue
    __shared__ ModeParams P;
    __shared__ float wTr[32], wTi[32], Ksh[Tn];

    // ---- phase 1: async u-tile (128 bc rows of this half) ----
    {
        const __half* vb = g_V + ((size_t)h * BC + half * 128) * 128;
        unsigned bsm = smem_u32(Bs);
        for (int i = tid; i < 128 * 16; i += 256) {
            int row = i >> 4, ch = i & 15;
            cp16(bsm + (unsigned)((row * LDB + ch * 8) * 2),
                 vb + (size_t)row * 128 + ch * 8);
        }
        cp_commit();
    }
    if (tid < 32) {
        compute_params(P, h, tid, log_dt, A_real, A_imag, C_real, C_imag);
        float erT = __expf(128.f * P.ar[tid]);
        float snT, csT;
        sincosf(128.f * P.ai[tid], &snT, &csT);
        wTr[tid] = erT * csT; wTi[tid] = erT * snT;
        // Ks[0] = 2*sum_n cr  (one-time warp reduce)
        float c2 = 2.0f * P.cr[tid];
#pragma unroll
        for (int off = 16; off; off >>= 1)
            c2 += __shfl_xor_sync(0xffffffffu, c2, off);
        if (tid == 0) Ksh[0] = c2;
    }
    __syncthreads();

    int n = tid & 31, w16 = tid >> 5;
    float ar = P.ar[n], ai = P.ai[n];
    float wr = P.wr[n], wi = P.wi[n];
    // base power w^{s0}, s0 = w16*16  (one transcendental set per thread)
    float s0 = (float)(w16 * 16);
    float pBr, pBi;
    {
        float er = __expf(s0 * ar);
        float sn, cs;
        sincosf(s0 * ai, &sn, &cs);
        pBr = er * cs; pBi = er * sn;
    }

    // ---- phase 2a: inline Enc into R1 (chained) ----
    __half* EncS = R1;
    {
        float pr = pBr, pi = pBi;
#pragma unroll
        for (int q = 0; q < 16; q++) {
            int s = w16 * 16 + q;
            EncS[n * LDA1 + (127 - s)]        = __float2half(pr);
            EncS[(n + 32) * LDA1 + (127 - s)] = __float2half(pi);
            float nr = pr * wr - pi * wi;
            float ni = pr * wi + pi * wr;
            pr = nr; pi = ni;
        }
    }
    cp_wait_all();
    __syncthreads();

    int wid = tid >> 5, lane = tid & 31;
    int la = lane & 15;
    int aRowOff = (lane < 16) ? lane : (lane - 16);
    int aColOff = (lane < 16) ? 0 : 8;
    int bRowOff = la & 7;
    int bColOff = (la >> 3) * 8;

    // ---- phase 2b: encode GEMM  Xl[64,128] = Enc @ B_u^T (double-buffered) ----
    {
        int wm = wid & 1, wn = wid >> 1;
        int m_base = wm * 32, n_base = wn * 32;

        float acc[2][4][4];
#pragma unroll
        for (int a = 0; a < 2; a++)
#pragma unroll
            for (int bI = 0; bI < 4; bI++)
#pragma unroll
                for (int cI = 0; cI < 4; cI++) acc[a][bI][cI] = 0.f;

        unsigned eaB = smem_u32(&EncS[(m_base + aRowOff) * LDA1 + aColOff]);
        unsigned ebB = smem_u32(&Bs[(n_base + bRowOff) * LDB + bColOff]);
        unsigned af[2][2][4];
        unsigned bf[2][4][2];

#define LOAD_E(buf, ks_)                                                      \
    {                                                                         \
        const int kk_ = (ks_) * 16;                                           \
        _Pragma("unroll")                                                     \
        for (int mf = 0; mf < 2; mf++)                                        \
            ldmA(eaB + (unsigned)((mf * 16 * LDA1 + kk_) * 2),                \
                 af[buf][mf][0], af[buf][mf][1], af[buf][mf][2], af[buf][mf][3]); \
        _Pragma("unroll")                                                     \
        for (int nf = 0; nf < 4; nf++)                                        \
            ldmB(ebB + (unsigned)((nf * 8 * LDB + kk_) * 2),                  \
                 bf[buf][nf][0], bf[buf][nf][1]);                             \
    }
#define MMA_E(buf)                                                            \
    {                                                                         \
        _Pragma("unroll")                                                     \
        for (int mf = 0; mf < 2; mf++)                                        \
            _Pragma("unroll")                                                 \
            for (int nf = 0; nf < 4; nf++)                                    \
                mma16816(acc[mf][nf], af[buf][mf], bf[buf][nf]);              \
    }
        LOAD_E(0, 0)
#pragma unroll
        for (int it = 0; it < 8; it++) {
            int cur = it & 1;
            if (it < 7) LOAD_E(cur ^ 1, it + 1)
            MMA_E(cur)
        }
#undef LOAD_E
#undef MMA_E
        __syncthreads();   // Enc reads done -> reuse R1 as Xl

        float* Xls = reinterpret_cast<float*>(R1);
        int r = lane >> 2, cp = lane & 3;
#pragma unroll
        for (int mf = 0; mf < 2; mf++) {
#pragma unroll
            for (int nf = 0; nf < 4; nf++) {
                int m = m_base + mf * 16 + r;
                int nn = n_base + nf * 8 + cp * 2;
                *reinterpret_cast<float2*>(&Xls[m * LDX + nn]) =
                    make_float2(acc[mf][nf][0], acc[mf][nf][1]);
                *reinterpret_cast<float2*>(&Xls[(m + 8) * LDX + nn]) =
                    make_float2(acc[mf][nf][2], acc[mf][nf][3]);
            }
        }
    }
    __syncthreads();

    // ---- phase 3: combine (4 sequences) -> fp16 states into Bs [128..192) ----
    if (tid < 128) {
        const float* Xls = reinterpret_cast<const float*>(R1);
        int bl = tid >> 5;      // local batch 0..3
        float wtr = wTr[n], wti = wTi[n];
        float XR = 0.f, XI = 0.f;
        const float* xR = &Xls[n * LDX];
        const float* xI = &Xls[(n + 32) * LDX];
#pragma unroll 4
        for (int c = 0; c < Cc; c++) {
            int bc = bl * Cc + c;             // local row 0..127
            Bs[bc * LDB + 128 + n] = __float2half(XR);
            Bs[bc * LDB + 160 + n] = __float2half(XI);
            float lr = xR[bc], li = xI[bc];
            float nR = wtr * XR - wti * XI + lr;
            float nI = wtr * XI + wti * XR + li;
            XR = nR; XI = nI;
        }
    }
    __syncthreads();   // Xl reads done -> reuse R1 as A panel

    // ---- phase 4a: inline A panel (Dec chained; Ks via Dec row-sum) ----
    __half* As = R1;
    {
        float cr = P.cr[n], ci = P.ci[n];
        // t = c' * w^{s0}
        float tr = cr * pBr - ci * pBi;
        float ti = cr * pBi + ci * pBr;
#pragma unroll
        for (int q = 0; q < 16; q++) {
            int sp = w16 * 16 + q;
            float dr = tr * wr - ti * wi;
            float di = tr * wi + ti * wr;               // c' w^{sp+1}
            As[sp * LDA2 + 128 + n] = __float2half(2.0f * dr);
            As[sp * LDA2 + 160 + n] = __float2half(-2.0f * di);
            tr = dr; ti = di;                           // advance chain
        }
    }
    __syncthreads();
    // Ks[s] (s>=1) = sum_n Dec[s-1][n]  (exact identity; fp16-rounded terms)
    if (tid >= 1 && tid < 128) {
        const __half2* row = reinterpret_cast<const __half2*>(
            &As[(tid - 1) * LDA2 + 128]);
        float s = 0.f;
#pragma unroll
        for (int k = 0; k < 16; k++) {
            float2 f = __half22float2(row[k]);
            s += f.x + f.y;
        }
        Ksh[tid] = s;
    }
    __syncthreads();
    for (int i = tid; i < 128 * 16; i += 256) {
        int row = i >> 4, ch = i & 15;
        int j0 = ch * 8;
        __half hv[8];
#pragma unroll
        for (int k = 0; k < 8; k++) {
            int j = j0 + k;
            hv[k] = __float2half((row >= j) ? Ksh[row - j] : 0.f);
        }
        *reinterpret_cast<uint4*>(&As[row * LDA2 + j0]) =
            *reinterpret_cast<const uint4*>(hv);
    }
    __syncthreads();

    // ---- phase 4b: main GEMM  Y[128,128] = [Toep|Dec] @ B^T ----
    int wm = wid >> 2, wn2 = wid & 3;    // balanced short/long warps per SMSP
    int m_base = wm * 64, n_base = wn2 * 32;
    unsigned aBase = smem_u32(&As[(m_base + aRowOff) * LDA2 + aColOff]);
    unsigned bBase = smem_u32(&Bs[(n_base + bRowOff) * LDB + bColOff]);

    float acc[4][4][4];
#pragma unroll
    for (int a = 0; a < 4; a++)
#pragma unroll
        for (int bI = 0; bI < 4; bI++)
#pragma unroll
            for (int cI = 0; cI < 4; cI++) acc[a][bI][cI] = 0.f;

    unsigned af[2][4][4];
    unsigned bf[2][4][2];

#define LOAD_AB(buf, ks_)                                                     \
    {                                                                         \
        const int kk_ = (ks_) * 16;                                           \
        _Pragma("unroll")                                                     \
        for (int mf = 0; mf < 4; mf++)                                        \
            ldmA(aBase + (unsigned)((mf * 16 * LDA2 + kk_) * 2),              \
                 af[buf][mf][0], af[buf][mf][1], af[buf][mf][2], af[buf][mf][3]); \
        _Pragma("unroll")                                                     \
        for (int nf = 0; nf < 4; nf++)                                        \
            ldmB(bBase + (unsigned)((nf * 8 * LDB + kk_) * 2),                \
                 bf[buf][nf][0], bf[buf][nf][1]);                             \
    }
#define MMA_STEP(buf)                                                         \
    {                                                                         \
        _Pragma("unroll")                                                     \
        for (int mf = 0; mf < 4; mf++)                                        \
            _Pragma("unroll")                                                 \
            for (int nf = 0; nf < 4; nf++)                                    \
                mma16816(acc[mf][nf], af[buf][mf], bf[buf][nf]);              \
    }

    if (wm == 0) {
        // rows m<64: Toeplitz cols 64..127 are zero -> k-steps {0..3, 8..11}
        LOAD_AB(0, 0)
#pragma unroll
        for (int it = 0; it < 8; it++) {
            int cur = it & 1;
            if (it < 7) {
                int nks = (it + 1 < 4) ? (it + 1) : (it + 5);
                LOAD_AB(cur ^ 1, nks)
            }
            MMA_STEP(cur)
        }
    } else {
        LOAD_AB(0, 0)
#pragma unroll
        for (int it = 0; it < 12; it++) {
            int cur = it & 1;
            if (it < 11) LOAD_AB(cur ^ 1, it + 1)
            MMA_STEP(cur)
        }
    }
#undef LOAD_AB
#undef MMA_STEP

    // ---- phase 5: epilogue -> stage fp16 in R1, coalesced global store ----
    __syncthreads();   // A-panel reads done -> reuse R1 as staging
    __half* ot = R1;   // [128 bc][LDO]
    {
        int r = lane >> 2, cp = lane & 3;
#pragma unroll
        for (int mf = 0; mf < 4; mf++) {
            int m = m_base + mf * 16 + r;
#pragma unroll
            for (int nf = 0; nf < 4; nf++) {
                int nn = n_base + nf * 8 + cp * 2;
                ot[nn * LDO + m]           = __float2half(acc[mf][nf][0]);
                ot[(nn + 1) * LDO + m]     = __float2half(acc[mf][nf][1]);
                ot[nn * LDO + m + 8]       = __float2half(acc[mf][nf][2]);
                ot[(nn + 1) * LDO + m + 8] = __float2half(acc[mf][nf][3]);
            }
        }
    }
    __syncthreads();
    {
        __half* dst = g_yT16 + ((size_t)h * BC + half * 128) * Tn;
        for (int i = tid; i < 128 * 16; i += 256) {
            int row = i >> 4, ch = i & 15;
            *reinterpret_cast<uint4*>(&dst[row * Tn + ch * 8]) =
                *reinterpret_cast<const uint4*>(&ot[row * LDO + ch * 8]);
        }
    }
}

// =====================================================================
// k_final: transpose yT16 -> (b,l,h), + D*u (skipped when D==0), GELU
// =====================================================================
__global__ void __launch_bounds__(256)
k_final(const float* __restrict__ u, const float* __restrict__ Dp,
        float* __restrict__ out, int ht0) {
    int ht = blockIdx.x + ht0, c = blockIdx.y, b = blockIdx.z;
    __shared__ float ys[128][33];
    int bc = b * Cc + c;

    {
#pragma unroll
        for (int q = 0; q < 2; q++) {
            int idx = threadIdx.x + q * 256;
            int row = idx >> 4;
            int ch = idx & 15;
            const uint4* src = reinterpret_cast<const uint4*>(
                g_yT16 + ((size_t)(ht * 32 + row) * BC + bc) * Tn);
            uint4 v = src[ch];
            const __half* hp = reinterpret_cast<const __half*>(&v);
            int i = ch * 8;
#pragma unroll
            for (int k = 0; k < 8; k++)
                ys[i + k][row] = __half2float(hp[k]);
        }
    }
    __syncthreads();

    float Dv = *Dp;
    int lane = threadIdx.x & 31;
    int r = threadIdx.x >> 5;
    size_t base = ((size_t)b * Ln + (size_t)c * Tn + r) * Hn + ht * 32 + lane;
    if (Dv != 0.0f) {
#pragma unroll
        for (int i0 = 0; i0 < Tn; i0 += 8) {
            int i = i0 + r;
            size_t gidx = base + (size_t)i0 * Hn;
            float v = ys[i][lane] + Dv * u[gidx];
            out[gidx] = gelu_erf(v);
        }
    } else {
#pragma unroll
        for (int i0 = 0; i0 < Tn; i0 += 8) {
            int i = i0 + r;
            size_t gidx = base + (size_t)i0 * Hn;
            out[gidx] = gelu_erf(ys[i][lane]);
        }
    }
}

// =====================================================================
// launch: two staggered h-half pipelines on two streams (fork/join)
// =====================================================================
extern "C" void kernel_launch(void* const* d_in, const int* in_sizes, int n_in,
                              void* d_out, int out_size) {
    (void)in_sizes; (void)n_in; (void)out_size;
    const float* u      = (const float*)d_in[0];
    const float* log_dt = (const float*)d_in[1];
    const float* A_real = (const float*)d_in[2];
    const float* A_imag = (const float*)d_in[3];
    const float* C_real = (const float*)d_in[4];
    const float* C_imag = (const float*)d_in[5];
    const float* D      = (const float*)d_in[6];
    float* out = (float*)d_out;

    static bool init_done = false;
    static cudaStream_t s2;
    static cudaEvent_t evT, evJoin;
    if (!init_done) {
        cudaFuncSetAttribute(k_fused, cudaFuncAttributeMaxDynamicSharedMemorySize,
                             SMEM_FUSED);
        // uniform carveout across all kernels: avoid smem-config reconfig
        // serialization between concurrent/adjacent launches
        cudaFuncSetAttribute(k_fused, cudaFuncAttributePreferredSharedMemoryCarveout, 100);
        cudaFuncSetAttribute(k_transpose, cudaFuncAttributePreferredSharedMemoryCarveout, 100);
        cudaFuncSetAttribute(k_final, cudaFuncAttributePreferredSharedMemoryCarveout, 100);
        cudaStreamCreateWithFlags(&s2, cudaStreamNonBlocking);
        cudaEventCreateWithFlags(&evT, cudaEventDisableTiming);
        cudaEventCreateWithFlags(&evJoin, cudaEventDisableTiming);
        init_done = true;
    }

    // Pipeline A (h 0..511) on the launch stream
    k_transpose<<<dim3(16, Cc, Bn), 256>>>(u, 0);
    cudaEventRecord(evT, 0);                 // fork point: T_A complete
    k_fused<<<dim3(512, 2), 256, SMEM_FUSED>>>(log_dt, A_real, A_imag,
                                               C_real, C_imag, 0);
    k_final<<<dim3(16, Cc, Bn), 256>>>(u, D, out, 0);

    // Pipeline B (h 512..1023) on s2, staggered after T_A
    cudaStreamWaitEvent(s2, evT, 0);
    k_transpose<<<dim3(16, Cc, Bn), 256, 0, s2>>>(u, 16);
    k_fused<<<dim3(512, 2), 256, SMEM_FUSED, s2>>>(log_dt, A_real, A_imag,
                                                   C_real, C_imag, 512);
    k_final<<<dim3(16, Cc, Bn), 256, 0, s2>>>(u, D, out, 16);

    // join back to the launch stream
    cudaEventRecord(evJoin, s2);
    cudaStreamWaitEvent(0, evJoin, 0);
}